// round 15
// baseline (speedup 1.0000x reference)
#include <cuda_runtime.h>
#include <cuda_fp16.h>
#include <math.h>
#include <stdint.h>

#define B_ 4096
#define D_ 256
#define SCALE_ 20.0f
#define KX_ 28.853900817779268f   // SCALE_ * log2(e), exp2 fold
#define NT_ 32          // N tiles (128 cols each)
#define MT_ 32          // M tiles (128 rows each)
#define NTILES_ 4096    // 4 pairs * 32 * 32

// ------------- scratch (device globals; no allocation) -------------
__device__ __align__(16) unsigned char g_nhf[4][4u * 4096u * 128u];   // 8 MB
__device__ float g_rowpart[4][NT_][B_];
__device__ float g_colpart[4][MT_][B_];
__device__ float g_diag[4][B_];
__device__ float g_blocksum[64];
__device__ int g_ticket;     // GEMM-CTA completion counter
__device__ int g_ticket2;    // finisher-slice counter

// pair slots: 0=anchor, 1=positive, 2=ref_pos_text, 3=ref_pos_vision
// pairs p=0..3: (0,1) (0,2) (1,2) (1,3) -> x = p>>1, y = (p+3)>>1

// ------------- PTX helpers (plain sm_80/90-level PTX; no 'a' features) -------------
__device__ __forceinline__ uint32_t smem_u32(const void* p) {
    uint32_t a;
    asm("{ .reg .u64 t; cvta.to.shared.u64 t, %1; cvt.u32.u64 %0, t; }" : "=r"(a) : "l"(p));
    return a;
}
__device__ __forceinline__ void mbar_init(uint32_t m, uint32_t cnt) {
    asm volatile("mbarrier.init.shared.b64 [%0], %1;" :: "r"(m), "r"(cnt) : "memory");
}
__device__ __forceinline__ void mbar_expect(uint32_t m, uint32_t tx) {
    asm volatile("mbarrier.arrive.expect_tx.shared.b64 _, [%0], %1;" :: "r"(m), "r"(tx) : "memory");
}
__device__ __forceinline__ void mbar_wait(uint32_t m, uint32_t ph) {
    asm volatile(
        "{\n\t.reg .pred P;\n"
        "WL_%=:\n\t"
        "mbarrier.try_wait.parity.shared.b64 P, [%0], %1;\n\t"
        "@!P bra WL_%=;\n"
        "}" :: "r"(m), "r"(ph) : "memory");
}
__device__ __forceinline__ void bulk_cp(uint32_t dst, const void* src, uint32_t bytes, uint32_t m) {
    asm volatile("cp.async.bulk.shared::cluster.global.mbarrier::complete_tx::bytes [%0], [%1], %2, [%3];"
                 :: "r"(dst), "l"(src), "r"(bytes), "r"(m) : "memory");
}
__device__ __forceinline__ void ldsm4(uint32_t* r, uint32_t addr) {
    asm volatile("ldmatrix.sync.aligned.m8n8.x4.shared.b16 {%0,%1,%2,%3}, [%4];"
                 : "=r"(r[0]), "=r"(r[1]), "=r"(r[2]), "=r"(r[3]) : "r"(addr));
}
// FP16 x FP16 -> FP16 acc
__device__ __forceinline__ void mma16816h(uint32_t* c, const uint32_t* a, uint32_t b0, uint32_t b1) {
    asm volatile("mma.sync.aligned.m16n8k16.row.col.f16.f16.f16.f16 "
                 "{%0,%1}, {%2,%3,%4,%5}, {%6,%7}, {%0,%1};"
                 : "+r"(c[0]), "+r"(c[1])
                 : "r"(a[0]), "r"(a[1]), "r"(a[2]), "r"(a[3]), "r"(b0), "r"(b1));
}
__device__ __forceinline__ float ex2_fast(float x) {
    float y;
    asm("ex2.approx.ftz.f32 %0, %1;" : "=f"(y) : "f"(x));
    return y;
}

// ------------- 1) normalize + emit preswizzled chunked f16 (2 rows per warp) -------------
// grid (256, 4), 256 threads: warp handles 2 rows -> 4 LDG.128 in flight.
__global__ void normalize_kernel(const float* __restrict__ a, const float* __restrict__ b,
                                 const float* __restrict__ c, const float* __restrict__ d) {
    const float* src = blockIdx.y == 0 ? a : blockIdx.y == 1 ? b : blockIdx.y == 2 ? c : d;
    int w = threadIdx.x >> 5, l = threadIdx.x & 31;
    int row0 = blockIdx.x * 16 + w * 2;
    const float* __restrict__ xa = src + (size_t)row0 * D_;
    const float* __restrict__ xb = src + (size_t)(row0 + 1) * D_;
    float4 a0 = *(const float4*)(xa + l * 8);
    float4 a1 = *(const float4*)(xa + l * 8 + 4);
    float4 b0 = *(const float4*)(xb + l * 8);
    float4 b1 = *(const float4*)(xb + l * 8 + 4);
    float sa = a0.x * a0.x + a0.y * a0.y + a0.z * a0.z + a0.w * a0.w
             + a1.x * a1.x + a1.y * a1.y + a1.z * a1.z + a1.w * a1.w;
    float sb = b0.x * b0.x + b0.y * b0.y + b0.z * b0.z + b0.w * b0.w
             + b1.x * b1.x + b1.y * b1.y + b1.z * b1.z + b1.w * b1.w;
    #pragma unroll
    for (int o = 16; o > 0; o >>= 1) {
        sa += __shfl_xor_sync(0xffffffffu, sa, o);
        sb += __shfl_xor_sync(0xffffffffu, sb, o);
    }
    float ra = rsqrtf(fmaxf(sa, 1e-24f));
    float rb = rsqrtf(fmaxf(sb, 1e-24f));
    unsigned char* dst = g_nhf[blockIdx.y];
    const uint32_t ch = (uint32_t)(l >> 3);
    const uint32_t j = (uint32_t)(l * 8) & 63u;
    #pragma unroll
    for (int rr = 0; rr < 2; rr++) {
        float4 v0 = rr ? b0 : a0;
        float4 v1 = rr ? b1 : a1;
        float r = rr ? rb : ra;
        uint32_t off = (ch * 4096u + (uint32_t)(row0 + rr)) * 128u + j * 2u;
        __half2 p0 = __floats2half2_rn(v0.x * r, v0.y * r);
        __half2 p1 = __floats2half2_rn(v0.z * r, v0.w * r);
        __half2 p2 = __floats2half2_rn(v1.x * r, v1.y * r);
        __half2 p3 = __floats2half2_rn(v1.z * r, v1.w * r);
        uint4 pk = make_uint4(*(uint32_t*)&p0, *(uint32_t*)&p1, *(uint32_t*)&p2, *(uint32_t*)&p3);
        *(uint4*)&dst[off ^ ((off >> 3) & 0x70u)] = pk;
    }
}

// ------------- 2) FP16 MMA GEMM + exp + partial sums + diag + FUSED finalize; 3 CTAs/SM -------------
// grid (32 jx, 32 iy, 4 pairs), 128 threads (2x2 warps, warp tile 64x64).
// CTA tile 128(M) x 128(N). K=256 in 4 chunks of 64; 2-stage 32KB pipeline.
#define STG_BYTES_ 32768u
#define SMEM_DYN_ (2 * 32768 + 1024)

__global__ __launch_bounds__(128, 3) void pair_gemm_mma(float* out, int out_size) {
    extern __shared__ __align__(16) unsigned char dyn_smem[];
    __shared__ float rowred[128 * 2];
    __shared__ float colred[128 * 2];
    __shared__ __align__(8) unsigned long long s_mbar[2];
    __shared__ int s_rank;
    __shared__ int s_final;
    __shared__ float ws[4];

    const int tid  = threadIdx.x;
    const int wid  = tid >> 5, lane = tid & 31;
    const int wm   = wid >> 1;            // 0..1  (M)
    const int wn   = wid & 1;             // 0..1  (N)
    const int p    = blockIdx.z;
    const int iy   = blockIdx.y, jx = blockIdx.x;
    const int i0   = iy * 128, j0 = jx * 128;
    const unsigned char* Abase = g_nhf[p >> 1]       + (size_t)i0 * 128u;
    const unsigned char* Bbase = g_nhf[(p + 3) >> 1] + (size_t)j0 * 128u;

    const uint32_t sbase = (smem_u32(dyn_smem) + 1023u) & ~1023u;
    uint32_t mfull[2] = {smem_u32(&s_mbar[0]), smem_u32(&s_mbar[1])};

    if (tid == 0) {
        mbar_init(mfull[0], 1u);
        mbar_init(mfull[1], 1u);
    }
    __syncthreads();

    if (tid == 0) {   // prologue: chunks 0,1 into stages 0,1
        #pragma unroll
        for (int c = 0; c < 2; c++) {
            mbar_expect(mfull[c], STG_BYTES_);
            bulk_cp(sbase + c * STG_BYTES_,          Abase + (size_t)c * 524288u, 16384u, mfull[c]);
            bulk_cp(sbase + c * STG_BYTES_ + 16384u, Bbase + (size_t)c * 524288u, 16384u, mfull[c]);
        }
    }

    // per-lane ldmatrix address components (byte-identical frag math to validated path)
    int a_row[4], a_xr[4];
    #pragma unroll
    for (int mi = 0; mi < 4; mi++) {
        int r = wm * 64 + mi * 16 + (lane & 15);
        a_row[mi] = r * 128;
        a_xr[mi] = (r & 7) << 4;
    }
    const int a_lk = (lane & 16) ? 16 : 0;
    int b_row[4], b_xr[4];
    #pragma unroll
    for (int n2 = 0; n2 < 4; n2++) {
        int r = wn * 64 + n2 * 16 + (lane & 7) + ((lane & 16) ? 8 : 0);
        b_row[n2] = r * 128;
        b_xr[n2] = (r & 7) << 4;
    }
    const int b_lk = (lane & 8) ? 16 : 0;

    uint32_t acc[4][8][2];   // f16x2 accumulators, warp tile 64x64
    #pragma unroll
    for (int mi = 0; mi < 4; mi++)
        #pragma unroll
        for (int ni = 0; ni < 8; ni++) {
            acc[mi][ni][0] = 0u;
            acc[mi][ni][1] = 0u;
        }

    #pragma unroll
    for (int c = 0; c < 4; c++) {
        const int stg = c & 1;                     // 2-stage ring
        const uint32_t abuf = sbase + (uint32_t)stg * STG_BYTES_;
        const uint32_t bbuf = abuf + 16384u;
        mbar_wait(mfull[stg], (c >> 1) & 1);

        #pragma unroll
        for (int ks = 0; ks < 4; ks++) {           // 16 f16 k-values per step
            const int kb = ks * 32;
            uint32_t a[4][4], b[4][4];
            #pragma unroll
            for (int mi = 0; mi < 4; mi++)
                ldsm4(a[mi], abuf + a_row[mi] + ((kb + a_lk) ^ a_xr[mi]));
            #pragma unroll
            for (int n2 = 0; n2 < 4; n2++)
                ldsm4(b[n2], bbuf + b_row[n2] + ((kb + b_lk) ^ b_xr[n2]));
            #pragma unroll
            for (int mi = 0; mi < 4; mi++)
                #pragma unroll
                for (int ni = 0; ni < 8; ni++)
                    mma16816h(acc[mi][ni], a[mi], b[ni >> 1][(ni & 1) * 2], b[ni >> 1][(ni & 1) * 2 + 1]);
        }
        if (c < 2) {                               // refill stage c with chunk c+2
            __syncthreads();
            if (tid == 0) {
                mbar_expect(mfull[stg], STG_BYTES_);
                bulk_cp(sbase + (uint32_t)stg * STG_BYTES_,
                        Abase + (size_t)(c + 2) * 524288u, 16384u, mfull[stg]);
                bulk_cp(sbase + (uint32_t)stg * STG_BYTES_ + 16384u,
                        Bbase + (size_t)(c + 2) * 524288u, 16384u, mfull[stg]);
            }
        }
    }

    // ---- tile epilogue ----
    if (iy == jx) {                                // tile holds global-diagonal entries
        #pragma unroll
        for (int mi = 0; mi < 4; mi++)
            #pragma unroll
            for (int q2 = 0; q2 < 2; q2++) {
                int rl = wm * 64 + mi * 16 + (lane >> 2) + 8 * q2;
                int cl = rl;
                if ((cl >> 6) == wn && (((cl >> 1) & 3) == (lane & 3))) {
                    int ni = (cl >> 3) & 7;
                    __half2 hv = *(__half2*)&acc[mi][ni][q2];
                    float v = (cl & 1) ? __high2float(hv) : __low2float(hv);
                    g_diag[p][i0 + rl] = SCALE_ * v;
                }
            }
    }

    float rs0[4], rs1[4], cs0[8], cs1[8];
    #pragma unroll
    for (int i = 0; i < 4; i++) { rs0[i] = rs1[i] = 0.f; }
    #pragma unroll
    for (int i = 0; i < 8; i++) { cs0[i] = cs1[i] = 0.f; }
    #pragma unroll
    for (int mi = 0; mi < 4; mi++)
        #pragma unroll
        for (int ni = 0; ni < 8; ni++) {
            float2 v01 = __half22float2(*(__half2*)&acc[mi][ni][0]);
            float2 v23 = __half22float2(*(__half2*)&acc[mi][ni][1]);
            float e0 = ex2_fast(KX_ * v01.x);
            float e1 = ex2_fast(KX_ * v01.y);
            float e2 = ex2_fast(KX_ * v23.x);
            float e3 = ex2_fast(KX_ * v23.y);
            rs0[mi] += e0 + e1;  rs1[mi] += e2 + e3;
            cs0[ni] += e0 + e2;  cs1[ni] += e1 + e3;
        }
    #pragma unroll
    for (int mi = 0; mi < 4; mi++) {
        rs0[mi] += __shfl_xor_sync(0xffffffffu, rs0[mi], 1);
        rs0[mi] += __shfl_xor_sync(0xffffffffu, rs0[mi], 2);
        rs1[mi] += __shfl_xor_sync(0xffffffffu, rs1[mi], 1);
        rs1[mi] += __shfl_xor_sync(0xffffffffu, rs1[mi], 2);
    }
    #pragma unroll
    for (int ni = 0; ni < 8; ni++) {
        #pragma unroll
        for (int h = 4; h <= 16; h <<= 1) {
            cs0[ni] += __shfl_xor_sync(0xffffffffu, cs0[ni], h);
            cs1[ni] += __shfl_xor_sync(0xffffffffu, cs1[ni], h);
        }
    }
    if ((lane & 3) == 0) {
        #pragma unroll
        for (int mi = 0; mi < 4; mi++) {
            int r = wm * 64 + mi * 16 + (lane >> 2);
            rowred[r * 2 + wn] = rs0[mi];
            rowred[(r + 8) * 2 + wn] = rs1[mi];
        }
    }
    if (lane < 4) {
        #pragma unroll
        for (int ni = 0; ni < 8; ni++) {
            int cbase = wn * 64 + ni * 8 + lane * 2;
            colred[cbase * 2 + wm] = cs0[ni];
            colred[(cbase + 1) * 2 + wm] = cs1[ni];
        }
    }
    __syncthreads();
    {
        float sr = rowred[tid * 2] + rowred[tid * 2 + 1];
        float sc = colred[tid * 2] + colred[tid * 2 + 1];
        g_rowpart[p][jx][i0 + tid] = sr;
        g_colpart[p][iy][j0 + tid] = sc;
    }

    // ---- fused finalize (threadfence-reduction) ----
    __threadfence();                               // publish this thread's partials
    __syncthreads();
    if (tid == 0) s_rank = atomicAdd(&g_ticket, 1);
    __syncthreads();
    const int rank = s_rank;
    if (rank < NTILES_ - 64) return;

    const int slice = NTILES_ - 1 - rank;          // 0..63, unique per finisher
    if (tid == 0) {
        volatile int* vt = &g_ticket;
        while (*vt < NTILES_) {}
    }
    __syncthreads();
    __threadfence();                               // acquire all partials

    float local = 0.f;
    #pragma unroll
    for (int u = 0; u < 2; u++) {
        int idx = slice * 256 + tid * 2 + u;       // 0..16383
        int pp = idx >> 12;
        int ii = idx & (B_ - 1);
        float rs = 0.f, cs = 0.f;
        #pragma unroll
        for (int x = 0; x < NT_; x++) {
            rs += __ldg(&g_rowpart[pp][x][ii]);
            cs += __ldg(&g_colpart[pp][x][ii]);
        }
        local += 0.5f * (logf(rs) + logf(cs)) - g_diag[pp][ii];
    }
    #pragma unroll
    for (int o = 16; o > 0; o >>= 1) local += __shfl_xor_sync(0xffffffffu, local, o);
    if (lane == 0) ws[wid] = local;
    __syncthreads();
    if (tid == 0) {
        g_blocksum[slice] = ws[0] + ws[1] + ws[2] + ws[3];
        __threadfence();
        s_final = (atomicAdd(&g_ticket2, 1) == 63);
    }
    __syncthreads();
    if (!s_final) return;

    // last finisher: final scalar + reset counters for graph replay
    __threadfence();
    __shared__ float loss;
    if (tid == 0) { g_ticket = 0; g_ticket2 = 0; }
    if (tid < 32) {
        float s = g_blocksum[tid] + g_blocksum[tid + 32];
        #pragma unroll
        for (int o = 16; o > 0; o >>= 1) s += __shfl_xor_sync(0xffffffffu, s, o);
        if (tid == 0) loss = s / (float)(B_ * 2);
    }
    __syncthreads();
    for (int i2 = tid; i2 < out_size; i2 += blockDim.x) out[i2] = loss;
}

// ------------- launch -------------
extern "C" void kernel_launch(void* const* d_in, const int* in_sizes, int n_in,
                              void* d_out, int out_size) {
    (void)in_sizes; (void)n_in;
    const float* A = (const float*)d_in[0];  // anchor
    const float* P = (const float*)d_in[1];  // positive
    // d_in[2] = reference_anchor: unused by the reference
    const float* T = (const float*)d_in[3];  // reference_positive_text
    const float* V = (const float*)d_in[4];  // reference_positive_vision

    cudaFuncSetAttribute(pair_gemm_mma, cudaFuncAttributeMaxDynamicSharedMemorySize, SMEM_DYN_);

    normalize_kernel<<<dim3(B_ / 16, 4), 256>>>(A, P, T, V);
    pair_gemm_mma<<<dim3(NT_, MT_, 4), 128, SMEM_DYN_>>>((float*)d_out, out_size);
}

// round 16
// speedup vs baseline: 1.0363x; 1.0363x over previous
#include <cuda_runtime.h>
#include <cuda_fp16.h>
#include <math.h>
#include <stdint.h>

#define B_ 4096
#define D_ 256
#define SCALE_ 20.0f
#define KX_ 28.853900817779268f   // SCALE_ * log2(e), exp2 fold
#define NT_ 32          // N tiles (128 cols each)
#define MT_ 32          // M tiles (128 rows each)

// ------------- scratch (device globals; no allocation) -------------
__device__ __align__(16) unsigned char g_nhf[4][4u * 4096u * 128u];   // 8 MB
__device__ float g_rowpart[4][NT_][B_];
__device__ float g_colpart[4][MT_][B_];
__device__ float g_diag[4][B_];
__device__ float g_blocksum[64];
__device__ int g_ticket;

// pair slots: 0=anchor, 1=positive, 2=ref_pos_text, 3=ref_pos_vision
// pairs p=0..3: (0,1) (0,2) (1,2) (1,3) -> x = p>>1, y = (p+3)>>1

// ------------- PTX helpers (plain sm_80/90-level PTX; no 'a' features) -------------
__device__ __forceinline__ uint32_t smem_u32(const void* p) {
    uint32_t a;
    asm("{ .reg .u64 t; cvta.to.shared.u64 t, %1; cvt.u32.u64 %0, t; }" : "=r"(a) : "l"(p));
    return a;
}
__device__ __forceinline__ void mbar_init(uint32_t m, uint32_t cnt) {
    asm volatile("mbarrier.init.shared.b64 [%0], %1;" :: "r"(m), "r"(cnt) : "memory");
}
__device__ __forceinline__ void mbar_expect(uint32_t m, uint32_t tx) {
    asm volatile("mbarrier.arrive.expect_tx.shared.b64 _, [%0], %1;" :: "r"(m), "r"(tx) : "memory");
}
__device__ __forceinline__ void mbar_arrive(uint32_t m) {
    asm volatile("mbarrier.arrive.shared.b64 _, [%0];" :: "r"(m) : "memory");
}
__device__ __forceinline__ void mbar_wait(uint32_t m, uint32_t ph) {
    asm volatile(
        "{\n\t.reg .pred P;\n"
        "WL_%=:\n\t"
        "mbarrier.try_wait.parity.shared.b64 P, [%0], %1;\n\t"
        "@!P bra WL_%=;\n"
        "}" :: "r"(m), "r"(ph) : "memory");
}
__device__ __forceinline__ void bulk_cp(uint32_t dst, const void* src, uint32_t bytes, uint32_t m) {
    asm volatile("cp.async.bulk.shared::cluster.global.mbarrier::complete_tx::bytes [%0], [%1], %2, [%3];"
                 :: "r"(dst), "l"(src), "r"(bytes), "r"(m) : "memory");
}
__device__ __forceinline__ void ldsm4(uint32_t* r, uint32_t addr) {
    asm volatile("ldmatrix.sync.aligned.m8n8.x4.shared.b16 {%0,%1,%2,%3}, [%4];"
                 : "=r"(r[0]), "=r"(r[1]), "=r"(r[2]), "=r"(r[3]) : "r"(addr));
}
// FP16 x FP16 -> FP16 acc
__device__ __forceinline__ void mma16816h(uint32_t* c, const uint32_t* a, uint32_t b0, uint32_t b1) {
    asm volatile("mma.sync.aligned.m16n8k16.row.col.f16.f16.f16.f16 "
                 "{%0,%1}, {%2,%3,%4,%5}, {%6,%7}, {%0,%1};"
                 : "+r"(c[0]), "+r"(c[1])
                 : "r"(a[0]), "r"(a[1]), "r"(a[2]), "r"(a[3]), "r"(b0), "r"(b1));
}
__device__ __forceinline__ float ex2_fast(float x) {
    float y;
    asm("ex2.approx.ftz.f32 %0, %1;" : "=f"(y) : "f"(x));
    return y;
}

// ------------- 1) normalize + emit preswizzled chunked f16 (warp-per-row, proven shape) -------------
__global__ void normalize_kernel(const float* __restrict__ a, const float* __restrict__ b,
                                 const float* __restrict__ c, const float* __restrict__ d) {
    const float* src = blockIdx.y == 0 ? a : blockIdx.y == 1 ? b : blockIdx.y == 2 ? c : d;
    int w = threadIdx.x >> 5, l = threadIdx.x & 31;
    int row = blockIdx.x * 8 + w;
    const float* __restrict__ x = src + (size_t)row * D_;
    float4 v0 = *(const float4*)(x + l * 8);
    float4 v1 = *(const float4*)(x + l * 8 + 4);
    float ss = v0.x * v0.x + v0.y * v0.y + v0.z * v0.z + v0.w * v0.w
             + v1.x * v1.x + v1.y * v1.y + v1.z * v1.z + v1.w * v1.w;
    #pragma unroll
    for (int o = 16; o > 0; o >>= 1) ss += __shfl_xor_sync(0xffffffffu, ss, o);
    float r = rsqrtf(fmaxf(ss, 1e-24f));
    unsigned char* dst = g_nhf[blockIdx.y];
    uint32_t ch = (uint32_t)(l >> 3);
    uint32_t j = (uint32_t)(l * 8) & 63u;
    uint32_t off = (ch * 4096u + (uint32_t)row) * 128u + j * 2u;
    __half2 p0 = __floats2half2_rn(v0.x * r, v0.y * r);
    __half2 p1 = __floats2half2_rn(v0.z * r, v0.w * r);
    __half2 p2 = __floats2half2_rn(v1.x * r, v1.y * r);
    __half2 p3 = __floats2half2_rn(v1.z * r, v1.w * r);
    uint4 pk = make_uint4(*(uint32_t*)&p0, *(uint32_t*)&p1, *(uint32_t*)&p2, *(uint32_t*)&p3);
    *(uint4*)&dst[off ^ ((off >> 3) & 0x70u)] = pk;
}

// ------------- 2) FP16 MMA GEMM + exp + row/col sums + diag; 3 CTAs/SM -------------
// grid (32 jx, 32 iy, 4 pairs), 128 threads (2x2 warps, warp tile 64x64).
// CTA tile 128(M) x 128(N). K=256 in 4 chunks of 64; 2-stage 32KB pipeline.
// Refill uses empty-mbarrier consumer-release (no block-wide barrier in mainloop).
#define STG_BYTES_ 32768u
#define SMEM_DYN_ (2 * 32768 + 1024)

__global__ __launch_bounds__(128, 3) void pair_gemm_mma() {
    extern __shared__ __align__(16) unsigned char dyn_smem[];
    __shared__ float rowred[128 * 2];
    __shared__ float colred[128 * 2];
    __shared__ __align__(8) unsigned long long s_mbar[4];  // full0 full1 empty0 empty1

    const int tid  = threadIdx.x;
    const int wid  = tid >> 5, lane = tid & 31;
    const int wm   = wid >> 1;            // 0..1  (M)
    const int wn   = wid & 1;             // 0..1  (N)
    const int p    = blockIdx.z;
    const int iy   = blockIdx.y, jx = blockIdx.x;
    const int i0   = iy * 128, j0 = jx * 128;
    const unsigned char* Abase = g_nhf[p >> 1]       + (size_t)i0 * 128u;
    const unsigned char* Bbase = g_nhf[(p + 3) >> 1] + (size_t)j0 * 128u;

    const uint32_t sbase = (smem_u32(dyn_smem) + 1023u) & ~1023u;
    uint32_t mfull[2]  = {smem_u32(&s_mbar[0]), smem_u32(&s_mbar[1])};
    uint32_t mempty[2] = {smem_u32(&s_mbar[2]), smem_u32(&s_mbar[3])};

    if (tid == 0) {
        mbar_init(mfull[0], 1u);
        mbar_init(mfull[1], 1u);
        mbar_init(mempty[0], 128u);
        mbar_init(mempty[1], 128u);
    }
    __syncthreads();

    if (tid == 0) {   // prologue: chunks 0,1 into stages 0,1
        #pragma unroll
        for (int c = 0; c < 2; c++) {
            mbar_expect(mfull[c], STG_BYTES_);
            bulk_cp(sbase + c * STG_BYTES_,          Abase + (size_t)c * 524288u, 16384u, mfull[c]);
            bulk_cp(sbase + c * STG_BYTES_ + 16384u, Bbase + (size_t)c * 524288u, 16384u, mfull[c]);
        }
    }

    // per-lane ldmatrix address components (byte-identical frag math to validated path)
    int a_row[4], a_xr[4];
    #pragma unroll
    for (int mi = 0; mi < 4; mi++) {
        int r = wm * 64 + mi * 16 + (lane & 15);
        a_row[mi] = r * 128;
        a_xr[mi] = (r & 7) << 4;
    }
    const int a_lk = (lane & 16) ? 16 : 0;
    int b_row[4], b_xr[4];
    #pragma unroll
    for (int n2 = 0; n2 < 4; n2++) {
        int r = wn * 64 + n2 * 16 + (lane & 7) + ((lane & 16) ? 8 : 0);
        b_row[n2] = r * 128;
        b_xr[n2] = (r & 7) << 4;
    }
    const int b_lk = (lane & 8) ? 16 : 0;

    uint32_t acc[4][8][2];   // f16x2 accumulators, warp tile 64x64
    #pragma unroll
    for (int mi = 0; mi < 4; mi++)
        #pragma unroll
        for (int ni = 0; ni < 8; ni++) {
            acc[mi][ni][0] = 0u;
            acc[mi][ni][1] = 0u;
        }

    #pragma unroll
    for (int c = 0; c < 4; c++) {
        const int stg = c & 1;                     // 2-stage ring
        const uint32_t abuf = sbase + (uint32_t)stg * STG_BYTES_;
        const uint32_t bbuf = abuf + 16384u;
        mbar_wait(mfull[stg], (c >> 1) & 1);

        #pragma unroll
        for (int ks = 0; ks < 4; ks++) {           // 16 f16 k-values per step
            const int kb = ks * 32;
            uint32_t a[4][4], b[4][4];
            #pragma unroll
            for (int mi = 0; mi < 4; mi++)
                ldsm4(a[mi], abuf + a_row[mi] + ((kb + a_lk) ^ a_xr[mi]));
            #pragma unroll
            for (int n2 = 0; n2 < 4; n2++)
                ldsm4(b[n2], bbuf + b_row[n2] + ((kb + b_lk) ^ b_xr[n2]));
            #pragma unroll
            for (int mi = 0; mi < 4; mi++)
                #pragma unroll
                for (int ni = 0; ni < 8; ni++)
                    mma16816h(acc[mi][ni], a[mi], b[ni >> 1][(ni & 1) * 2], b[ni >> 1][(ni & 1) * 2 + 1]);
        }
        if (c < 2) {
            // consumer-release: non-blocking arrive; only tid 0 waits, then refills.
            mbar_arrive(mempty[stg]);
            if (tid == 0) {
                mbar_wait(mempty[stg], 0u);
                mbar_expect(mfull[stg], STG_BYTES_);
                bulk_cp(sbase + (uint32_t)stg * STG_BYTES_,
                        Abase + (size_t)(c + 2) * 524288u, 16384u, mfull[stg]);
                bulk_cp(sbase + (uint32_t)stg * STG_BYTES_ + 16384u,
                        Bbase + (size_t)(c + 2) * 524288u, 16384u, mfull[stg]);
            }
        }
    }

    // ---- epilogue ----
    if (iy == jx) {                                // tile holds global-diagonal entries
        #pragma unroll
        for (int mi = 0; mi < 4; mi++)
            #pragma unroll
            for (int q2 = 0; q2 < 2; q2++) {
                int rl = wm * 64 + mi * 16 + (lane >> 2) + 8 * q2;
                int cl = rl;
                if ((cl >> 6) == wn && (((cl >> 1) & 3) == (lane & 3))) {
                    int ni = (cl >> 3) & 7;
                    __half2 hv = *(__half2*)&acc[mi][ni][q2];
                    float v = (cl & 1) ? __high2float(hv) : __low2float(hv);
                    g_diag[p][i0 + rl] = SCALE_ * v;
                }
            }
    }

    float rs0[4], rs1[4], cs0[8], cs1[8];
    #pragma unroll
    for (int i = 0; i < 4; i++) { rs0[i] = rs1[i] = 0.f; }
    #pragma unroll
    for (int i = 0; i < 8; i++) { cs0[i] = cs1[i] = 0.f; }
    #pragma unroll
    for (int mi = 0; mi < 4; mi++)
        #pragma unroll
        for (int ni = 0; ni < 8; ni++) {
            float2 v01 = __half22float2(*(__half2*)&acc[mi][ni][0]);  // (r,c) (r,c+1)
            float2 v23 = __half22float2(*(__half2*)&acc[mi][ni][1]);  // (r+8,c) (r+8,c+1)
            float e0 = ex2_fast(KX_ * v01.x);
            float e1 = ex2_fast(KX_ * v01.y);
            float e2 = ex2_fast(KX_ * v23.x);
            float e3 = ex2_fast(KX_ * v23.y);
            rs0[mi] += e0 + e1;  rs1[mi] += e2 + e3;
            cs0[ni] += e0 + e2;  cs1[ni] += e1 + e3;
        }
    #pragma unroll
    for (int mi = 0; mi < 4; mi++) {
        rs0[mi] += __shfl_xor_sync(0xffffffffu, rs0[mi], 1);
        rs0[mi] += __shfl_xor_sync(0xffffffffu, rs0[mi], 2);
        rs1[mi] += __shfl_xor_sync(0xffffffffu, rs1[mi], 1);
        rs1[mi] += __shfl_xor_sync(0xffffffffu, rs1[mi], 2);
    }
    #pragma unroll
    for (int ni = 0; ni < 8; ni++) {
        #pragma unroll
        for (int h = 4; h <= 16; h <<= 1) {
            cs0[ni] += __shfl_xor_sync(0xffffffffu, cs0[ni], h);
            cs1[ni] += __shfl_xor_sync(0xffffffffu, cs1[ni], h);
        }
    }
    if ((lane & 3) == 0) {
        #pragma unroll
        for (int mi = 0; mi < 4; mi++) {
            int r = wm * 64 + mi * 16 + (lane >> 2);
            rowred[r * 2 + wn] = rs0[mi];
            rowred[(r + 8) * 2 + wn] = rs1[mi];
        }
    }
    if (lane < 4) {
        #pragma unroll
        for (int ni = 0; ni < 8; ni++) {
            int cbase = wn * 64 + ni * 8 + lane * 2;
            colred[cbase * 2 + wm] = cs0[ni];
            colred[(cbase + 1) * 2 + wm] = cs1[ni];
        }
    }
    __syncthreads();
    {
        float sr = rowred[tid * 2] + rowred[tid * 2 + 1];
        float sc = colred[tid * 2] + colred[tid * 2 + 1];
        g_rowpart[p][jx][i0 + tid] = sr;
        g_colpart[p][iy][j0 + tid] = sc;
    }
}

// ------------- 3) fused finalize: per-row terms + ticketed final scalar -------------
__global__ void finalize_kernel(float* out, int out_size) {
    int idx = blockIdx.x * 256 + threadIdx.x;    // 0..16383
    int p = idx >> 12;
    int i = idx & (B_ - 1);
    float rs = 0.f, cs = 0.f;
    #pragma unroll
    for (int x = 0; x < NT_; x++) {
        rs += __ldg(&g_rowpart[p][x][i]);
        cs += __ldg(&g_colpart[p][x][i]);
    }
    float term = 0.5f * (logf(rs) + logf(cs)) - g_diag[p][i];
    #pragma unroll
    for (int o = 16; o > 0; o >>= 1) term += __shfl_xor_sync(0xffffffffu, term, o);
    __shared__ float ws[8];
    __shared__ int s_last;
    if ((threadIdx.x & 31) == 0) ws[threadIdx.x >> 5] = term;
    __syncthreads();
    if (threadIdx.x == 0) {
        float s = 0.f;
        #pragma unroll
        for (int q = 0; q < 8; q++) s += ws[q];
        g_blocksum[blockIdx.x] = s;
        __threadfence();
        s_last = (atomicAdd(&g_ticket, 1) == 63);
    }
    __syncthreads();
    if (s_last) {
        __shared__ float loss;
        if (threadIdx.x == 0) g_ticket = 0;        // reset for next graph replay
        __threadfence();
        if (threadIdx.x < 32) {
            float s = g_blocksum[threadIdx.x] + g_blocksum[threadIdx.x + 32];
            #pragma unroll
            for (int o = 16; o > 0; o >>= 1) s += __shfl_xor_sync(0xffffffffu, s, o);
            if (threadIdx.x == 0) loss = s / (float)(B_ * 2);
        }
        __syncthreads();
        for (int i2 = threadIdx.x; i2 < out_size; i2 += blockDim.x) out[i2] = loss;
    }
}

// ------------- launch -------------
extern "C" void kernel_launch(void* const* d_in, const int* in_sizes, int n_in,
                              void* d_out, int out_size) {
    (void)in_sizes; (void)n_in;
    const float* A = (const float*)d_in[0];  // anchor
    const float* P = (const float*)d_in[1];  // positive
    // d_in[2] = reference_anchor: unused by the reference
    const float* T = (const float*)d_in[3];  // reference_positive_text
    const float* V = (const float*)d_in[4];  // reference_positive_vision

    cudaFuncSetAttribute(pair_gemm_mma, cudaFuncAttributeMaxDynamicSharedMemorySize, SMEM_DYN_);

    normalize_kernel<<<dim3(B_ / 8, 4), 256>>>(A, P, T, V);
    pair_gemm_mma<<<dim3(NT_, MT_, 4), 128, SMEM_DYN_>>>();
    finalize_kernel<<<64, 256>>>((float*)d_out, out_size);
}